// round 14
// baseline (speedup 1.0000x reference)
#include <cuda_runtime.h>
#include <cuda_fp16.h>
#include <cstdint>

#define BATCH 32
#define SEQ   512
#define DD    1024
#define BS_TOT (BATCH*SEQ)      // 16384
#define LD    1024              // all scratch fp16, stride 1024
#define TM    128
#define TN    128
#define KTILE 64
#define NCHUNK (DD/KTILE)       // 16
#define THREADS 128

#define OFF_B       16384
#define STAGE_BYTES 32768
#define NSTAGE 3
#define SMEM_TOTAL (NSTAGE*STAGE_BYTES)   // 96KB -> 2 CTAs/SM

#define N_MT     128
#define N_NB     8
// bid layout (all 128-thread blocks):
#define N_TRANSU 1024                        // one 32x32 U tile each
#define N_PREP   4096                        // 4 rows each (32 blocks / m-tile)
#define N_G1     1024
#define N_G2     512
#define BASE_PREP (N_TRANSU)                 // 1024
#define BASE_G1   (BASE_PREP + N_PREP)       // 5120
#define BASE_G2   (BASE_G1 + N_G1)           // 6144
#define N_BLOCKS  (BASE_G2 + N_G2)           // 6656

// ---------------- scratch (static __device__, allocation-free) ----------------
__device__ __half g_Ds [(size_t)BS_TOT * LD];
__device__ __half g_Hs [(size_t)BS_TOT * LD];
__device__ __half g_Ts [(size_t)BS_TOT * LD];
__device__ __half g_Uts[(size_t)DD     * LD];
__device__ float g_rowlin[BS_TOT];
__device__ float g_collin[BS_TOT];
__device__ int   g_prep_done[N_MT];       // target 32
__device__ int   g_transU_done[N_NB];     // target 128
__device__ int   g_gemm1_done[N_MT];      // target 8

// ---------------- PTX helpers (family-portable: sm_80+) ----------------
#define CP_ASYNC16(smem_u32, gptr) \
    asm volatile("cp.async.cg.shared.global [%0], [%1], 16;" :: "r"(smem_u32), "l"(gptr))
#define CP_COMMIT()  asm volatile("cp.async.commit_group;" ::: "memory")
#define CP_WAIT0()   asm volatile("cp.async.wait_group 0;" ::: "memory")
#define CP_WAIT1()   asm volatile("cp.async.wait_group 1;" ::: "memory")

#define LDSM4(r0,r1,r2,r3,addr) \
    asm volatile("ldmatrix.sync.aligned.m8n8.x4.shared.b16 {%0,%1,%2,%3}, [%4];" \
        : "=r"(r0),"=r"(r1),"=r"(r2),"=r"(r3) : "r"(addr))

#define MMA16816(d, a, b0, b1) \
    asm volatile("mma.sync.aligned.m16n8k16.row.col.f32.f16.f16.f32 " \
        "{%0,%1,%2,%3}, {%4,%5,%6,%7}, {%8,%9}, {%0,%1,%2,%3};" \
        : "+f"((d)[0]),"+f"((d)[1]),"+f"((d)[2]),"+f"((d)[3]) \
        : "r"((a)[0]),"r"((a)[1]),"r"((a)[2]),"r"((a)[3]),"r"((b0)),"r"((b1)))

__device__ __forceinline__ uint32_t smem_u32_of(const void* p) {
    uint32_t a;
    asm("{ .reg .u64 t; cvta.to.shared.u64 t, %1; cvt.u32.u64 %0, t; }" : "=r"(a) : "l"(p));
    return a;
}
__device__ __forceinline__ int ld_acquire(const int* p) {
    int v;
    asm volatile("ld.global.acquire.gpu.b32 %0, [%1];" : "=r"(v) : "l"(p) : "memory");
    return v;
}
__device__ __forceinline__ void red_release(int* p, int v) {
    asm volatile("red.release.gpu.global.add.s32 [%0], %1;" :: "l"(p), "r"(v) : "memory");
}

__device__ __forceinline__ uint32_t pack_h2(float f0, float f1) {
    __half h0 = __float2half_rn(f0);
    __half h1 = __float2half_rn(f1);
    return (uint32_t)__half_as_ushort(h0) | ((uint32_t)__half_as_ushort(h1) << 16);
}
__device__ __forceinline__ void store_hi4(__half* dst, float4 v) {
    *(uint2*)dst = make_uint2(pack_h2(v.x, v.y), pack_h2(v.z, v.w));
}

// ---------------------------------------------------------------------------
// cp.async tile loader (A 128x128B, B 128x128B per chunk, SW128 swizzle)
// ---------------------------------------------------------------------------
__device__ __forceinline__ void load_tiles(uint32_t stage_base,
    const __half* __restrict__ A, const __half* __restrict__ B, int c)
{
    const int tid = threadIdx.x;
    #pragma unroll
    for (int i = 0; i < 8; ++i) {
        int idx = tid + i * THREADS;
        int row = idx >> 3, j = idx & 7;
        uint32_t d = (uint32_t)(row * 128 + ((j * 16) ^ ((row & 7) << 4)));
        CP_ASYNC16(stage_base + d,         A + (size_t)row * LD + c * KTILE + j * 8);
        CP_ASYNC16(stage_base + OFF_B + d, B + (size_t)row * LD + c * KTILE + j * 8);
    }
}

// ---------------------------------------------------------------------------
// Mainloop: acc[4][8][4] += A[128xK] * B[128xK]^T  (fp16 in, fp32 accum)
// 4 warps 2m x 2n, warp tile 64x64, 3-stage cp.async pipeline.
// ---------------------------------------------------------------------------
__device__ __forceinline__ void hmma_mainloop(uint32_t smem_base,
    const __half* __restrict__ Arows,
    const __half* __restrict__ Brows,
    float acc[4][8][4])
{
    const int tid  = threadIdx.x;
    const int lane = tid & 31, wid = tid >> 5;
    const int wm = wid >> 1, wn = wid & 1;

    const uint32_t aOff = (uint32_t)((wm * 64 + (lane & 15)) * 128);
    const uint32_t aKb  = (uint32_t)((lane >> 4) * 16);
    const uint32_t bOff = (uint32_t)((wn * 64 + ((lane >> 4) << 3) + (lane & 7)) * 128);
    const uint32_t bKb  = (uint32_t)(((lane >> 3) & 1) * 16);
    const uint32_t swz  = (uint32_t)((lane & 7) << 4);

    load_tiles(smem_base,               Arows, Brows, 0); CP_COMMIT();
    load_tiles(smem_base + STAGE_BYTES, Arows, Brows, 1); CP_COMMIT();

    for (int c = 0; c < NCHUNK; ++c) {
        if (c + 1 < NCHUNK) { CP_WAIT1(); } else { CP_WAIT0(); }
        __syncthreads();
        if (c + 2 < NCHUNK) {
            load_tiles(smem_base + ((c + 2) % NSTAGE) * STAGE_BYTES, Arows, Brows, c + 2);
            CP_COMMIT();
        }

        const uint32_t bufA = smem_base + (c % NSTAGE) * STAGE_BYTES;
        const uint32_t bufB = bufA + OFF_B;

        #pragma unroll
        for (int ks = 0; ks < 4; ++ks) {
            const uint32_t ak = (uint32_t)(ks * 32 + aKb) ^ swz;
            const uint32_t bk = (uint32_t)(ks * 32 + bKb) ^ swz;
            uint32_t a[4][4], b[4][4];
            #pragma unroll
            for (int fm = 0; fm < 4; ++fm) {
                uint32_t ad = bufA + aOff + fm * 2048 + ak;
                LDSM4(a[fm][0], a[fm][1], a[fm][2], a[fm][3], ad);
            }
            #pragma unroll
            for (int g = 0; g < 4; ++g) {
                uint32_t bd = bufB + bOff + g * 2048 + bk;
                LDSM4(b[g][0], b[g][1], b[g][2], b[g][3], bd);
            }
            #pragma unroll
            for (int fm = 0; fm < 4; ++fm) {
                #pragma unroll
                for (int fn = 0; fn < 8; ++fn) {
                    const int g = fn >> 1, p = (fn & 1) * 2;
                    MMA16816(acc[fm][fn], a[fm], b[g][p], b[g][p + 1]);
                }
            }
        }
    }
    __syncthreads();
}

// ---------------------------------------------------------------------------
// Single fused grid: transU | prep | gemm1 | gemm2, dependency-chained.
// prep is ILP-restructured: all 16 LDG.128 issued before converts/stores so
// DRAM saturates even at 2 CTAs/SM (8 warps).
// ---------------------------------------------------------------------------
__global__ __launch_bounds__(THREADS, 2)
void mega_kernel(const float* __restrict__ D, const float* __restrict__ Hf,
                 const float* __restrict__ U, const float* __restrict__ W,
                 __half* __restrict__ Ds, __half* __restrict__ Hs,
                 __half* __restrict__ Ts, __half* __restrict__ Uts,
                 float* __restrict__ rowlin, float* __restrict__ collin,
                 float* __restrict__ out)
{
    extern __shared__ char smem[];
    uint32_t smem_base = smem_u32_of(smem);
    const int bid = blockIdx.x;
    const int tid = threadIdx.x;
    const int lane = tid & 31, wid = tid >> 5;

    if (bid < BASE_PREP) {
        // ---- transU: one 32x32 tile ----
        float* t = (float*)smem;             // 32x33 staging
        const int n0 = (bid & 31) * 32, k0 = (bid >> 5) * 32;
        const int tx = lane, ty = wid;       // (32, 4)
        #pragma unroll
        for (int i = ty; i < 32; i += 4)
            t[i * 33 + tx] = U[(size_t)(k0 + i) * DD + n0 + tx];
        __syncthreads();
        #pragma unroll
        for (int i = ty; i < 32; i += 4)
            Uts[(size_t)(n0 + i) * LD + (k0 + tx)] = __float2half_rn(t[tx * 33 + i]);
        __syncthreads();
        if (tid == 0) red_release(&g_transU_done[n0 >> 7], 1);

    } else if (bid < BASE_G1) {
        // ---- prep: 4 rows (one per warp), front-loaded MLP=16 ----
        const size_t m = (size_t)(bid - BASE_PREP) * 4 + wid;
        const float* drow = D + m * DD;
        const float* hrow = Hf + m * DD;
        __half* dd = Ds + m * LD;
        __half* dh = Hs + m * LD;

        // issue all 16 independent LDG.128 first
        float4 dv[8], hv[8];
        #pragma unroll
        for (int i = 0; i < 8; ++i)
            dv[i] = *(const float4*)(drow + i * 128 + lane * 4);
        #pragma unroll
        for (int i = 0; i < 8; ++i)
            hv[i] = *(const float4*)(hrow + i * 128 + lane * 4);

        float s1 = 0.f, s2 = 0.f;
        #pragma unroll
        for (int i = 0; i < 8; ++i) {
            const int c = i * 128 + lane * 4;
            float4 wv = *(const float4*)(W + c);          // W[0:1024] aligned, L1-hot
            float w20 = __ldg(W + DD + 1 + c);
            float w21 = __ldg(W + DD + 2 + c);
            float w22 = __ldg(W + DD + 3 + c);
            float w23 = __ldg(W + DD + 4 + c);

            s1 = fmaf(dv[i].x, wv.x, fmaf(dv[i].y, wv.y,
                 fmaf(dv[i].z, wv.z, fmaf(dv[i].w, wv.w, s1))));
            s2 = fmaf(hv[i].x, w20, fmaf(hv[i].y, w21,
                 fmaf(hv[i].z, w22, fmaf(hv[i].w, w23, s2))));

            store_hi4(dd + c, dv[i]);
            store_hi4(dh + c, hv[i]);
        }
        #pragma unroll
        for (int o = 16; o > 0; o >>= 1) {
            s1 += __shfl_down_sync(0xffffffffu, s1, o);
            s2 += __shfl_down_sync(0xffffffffu, s2, o);
        }
        if (lane == 0) {
            rowlin[m] = s1 + W[DD];
            collin[m] = s2;
        }
        __syncthreads();
        if (tid == 0) red_release(&g_prep_done[(bid - BASE_PREP) >> 5], 1);

    } else if (bid < BASE_G2) {
        // ---- gemm1 tile: T = Daug @ U (+bias), store fp16 ----
        const int g  = bid - BASE_G1;
        const int mt = g >> 3, nb = g & 7;
        if (tid == 0) {
            while (ld_acquire(&g_prep_done[mt])   < 32)  __nanosleep(64);
            while (ld_acquire(&g_transU_done[nb]) < 128) __nanosleep(64);
        }
        __syncthreads();

        const size_t mBase = (size_t)mt * TM;
        const size_t nBase = (size_t)nb * TN;
        const float* Ubias = U + (size_t)DD * DD;

        float acc[4][8][4] = {};
        hmma_mainloop(smem_base, Ds + mBase * LD, Uts + nBase * LD, acc);

        const int wm = wid >> 1, wn = wid & 1;
        #pragma unroll
        for (int fm = 0; fm < 4; ++fm) {
            const size_t r0 = mBase + wm * 64 + fm * 16 + (lane >> 2);
            #pragma unroll
            for (int fn = 0; fn < 8; ++fn) {
                const size_t n = nBase + wn * 64 + fn * 8 + 2 * (lane & 3);
                const float b0 = Ubias[n], b1 = Ubias[n + 1];
                #pragma unroll
                for (int h = 0; h < 2; ++h) {
                    const size_t r = r0 + h * 8;
                    *(uint32_t*)(Ts + r * LD + n) =
                        pack_h2(acc[fm][fn][2 * h] + b0, acc[fm][fn][2 * h + 1] + b1);
                }
            }
        }
        __syncthreads();
        if (tid == 0) red_release(&g_gemm1_done[mt], 1);

    } else {
        // ---- gemm2 tile: out = T @ H^T + rowlin + collin ----
        const int g   = bid - BASE_G2;
        const int y   = g & 3;
        const int mtx = g >> 2;              // ascending with bid
        const int b   = mtx >> 2, x = mtx & 3;
        const int mty = b * 4 + y;

        if (tid == 0) {
            while (ld_acquire(&g_gemm1_done[mtx]) < 8)  __nanosleep(64);
            while (ld_acquire(&g_prep_done[mty])  < 32) __nanosleep(64);
        }
        __syncthreads();

        const size_t xBase = (size_t)x * TM;
        const size_t yBase = (size_t)y * TN;

        float acc[4][8][4] = {};
        hmma_mainloop(smem_base,
                      Ts + ((size_t)b * SEQ + xBase) * LD,
                      Hs + ((size_t)b * SEQ + yBase) * LD, acc);

        const int wm = wid >> 1, wn = wid & 1;
        #pragma unroll
        for (int fm = 0; fm < 4; ++fm) {
            const size_t x0 = xBase + wm * 64 + fm * 16 + (lane >> 2);
            #pragma unroll
            for (int h = 0; h < 2; ++h) {
                const size_t gx = (size_t)b * SEQ + x0 + h * 8;
                const float rl = rowlin[gx];
                #pragma unroll
                for (int fn = 0; fn < 8; ++fn) {
                    const size_t yy = yBase + wn * 64 + fn * 8 + 2 * (lane & 3);
                    const float c0 = collin[(size_t)b * SEQ + yy];
                    const float c1 = collin[(size_t)b * SEQ + yy + 1];
                    float2 o;
                    o.x = acc[fm][fn][2 * h]     + rl + c0;
                    o.y = acc[fm][fn][2 * h + 1] + rl + c1;
                    *(float2*)(out + gx * SEQ + yy) = o;
                }
            }
        }
    }
}

// zero queue counters (must run before mega_kernel on every call)
__global__ void zero_kernel()
{
    const int t = threadIdx.x;
    if (t < N_MT)  { g_prep_done[t] = 0; g_gemm1_done[t] = 0; }
    if (t < N_NB)    g_transU_done[t] = 0;
}

// ---------------------------------------------------------------------------
extern "C" void kernel_launch(void* const* d_in, const int* in_sizes, int n_in,
                              void* d_out, int out_size)
{
    const float* D = (const float*)d_in[0];   // [32,512,1024]
    const float* H = (const float*)d_in[1];   // [32,512,1024]
    const float* U = (const float*)d_in[2];   // [1025,1024]
    const float* W = (const float*)d_in[3];   // [2049]
    float* out = (float*)d_out;               // [32,512,512]

    __half *Ds, *Hs, *Ts, *Uts;
    float *rowlin, *collin;
    cudaGetSymbolAddress((void**)&Ds,  g_Ds);
    cudaGetSymbolAddress((void**)&Hs,  g_Hs);
    cudaGetSymbolAddress((void**)&Ts,  g_Ts);
    cudaGetSymbolAddress((void**)&Uts, g_Uts);
    cudaGetSymbolAddress((void**)&rowlin, g_rowlin);
    cudaGetSymbolAddress((void**)&collin, g_collin);

    cudaFuncSetAttribute(mega_kernel, cudaFuncAttributeMaxDynamicSharedMemorySize, SMEM_TOTAL);

    zero_kernel<<<1, N_MT>>>();
    mega_kernel<<<N_BLOCKS, THREADS, SMEM_TOTAL>>>(
        D, H, U, W, Ds, Hs, Ts, Uts, rowlin, collin, out);
}

// round 15
// speedup vs baseline: 1.1258x; 1.1258x over previous
#include <cuda_runtime.h>
#include <cuda_fp16.h>
#include <cstdint>

#define BATCH 32
#define SEQ   512
#define DD    1024
#define BS_TOT (BATCH*SEQ)      // 16384
#define LD    1024              // all scratch fp16, stride 1024
#define TM    128
#define TN    128
#define KTILE 64
#define NCHUNK (DD/KTILE)       // 16
#define THREADS 128

#define OFF_B       16384
#define STAGE_BYTES 32768
#define NSTAGE 3
#define SMEM_TOTAL (NSTAGE*STAGE_BYTES)   // 96KB -> 2 CTAs/SM

#define N_MT   128               // m-tiles
#define N_NB   8                 // U n-tiles (128 cols each)
#define N_G1   1024
#define N_G2   512
#define PREP_BLOCKS   2048       // 8 rows each -> 16 blocks per m-tile
#define TRANSU_BLOCKS 1024       // one 32x32 tile each -> 128 per nb

// ---------------- scratch (static __device__, allocation-free) ----------------
__device__ __half g_Ds [(size_t)BS_TOT * LD];
__device__ __half g_Hs [(size_t)BS_TOT * LD];
__device__ __half g_Ts [(size_t)BS_TOT * LD];
__device__ __half g_Uts[(size_t)DD     * LD];
__device__ float g_rowlin[BS_TOT];
__device__ float g_collin[BS_TOT];
__device__ int   g_prep_done[N_MT];       // target 16
__device__ int   g_transU_done[N_NB];     // target 128
__device__ int   g_gemm1_done[N_MT];      // target 8

// ---------------- PTX helpers (family-portable: sm_80+/sm_90+) ----------------
#define CP_ASYNC16(smem_u32, gptr) \
    asm volatile("cp.async.cg.shared.global [%0], [%1], 16;" :: "r"(smem_u32), "l"(gptr))
#define CP_COMMIT()  asm volatile("cp.async.commit_group;" ::: "memory")
#define CP_WAIT0()   asm volatile("cp.async.wait_group 0;" ::: "memory")
#define CP_WAIT1()   asm volatile("cp.async.wait_group 1;" ::: "memory")

#define LDSM4(r0,r1,r2,r3,addr) \
    asm volatile("ldmatrix.sync.aligned.m8n8.x4.shared.b16 {%0,%1,%2,%3}, [%4];" \
        : "=r"(r0),"=r"(r1),"=r"(r2),"=r"(r3) : "r"(addr))

#define MMA16816(d, a, b0, b1) \
    asm volatile("mma.sync.aligned.m16n8k16.row.col.f32.f16.f16.f32 " \
        "{%0,%1,%2,%3}, {%4,%5,%6,%7}, {%8,%9}, {%0,%1,%2,%3};" \
        : "+f"((d)[0]),"+f"((d)[1]),"+f"((d)[2]),"+f"((d)[3]) \
        : "r"((a)[0]),"r"((a)[1]),"r"((a)[2]),"r"((a)[3]),"r"((b0)),"r"((b1)))

__device__ __forceinline__ uint32_t smem_u32_of(const void* p) {
    uint32_t a;
    asm("{ .reg .u64 t; cvta.to.shared.u64 t, %1; cvt.u32.u64 %0, t; }" : "=r"(a) : "l"(p));
    return a;
}
__device__ __forceinline__ int ld_acquire(const int* p) {
    int v;
    asm volatile("ld.global.acquire.gpu.b32 %0, [%1];" : "=r"(v) : "l"(p) : "memory");
    return v;
}
__device__ __forceinline__ void red_release(int* p, int v) {
    asm volatile("red.release.gpu.global.add.s32 [%0], %1;" :: "l"(p), "r"(v) : "memory");
}

__device__ __forceinline__ uint32_t pack_h2(float f0, float f1) {
    __half h0 = __float2half_rn(f0);
    __half h1 = __float2half_rn(f1);
    return (uint32_t)__half_as_ushort(h0) | ((uint32_t)__half_as_ushort(h1) << 16);
}
__device__ __forceinline__ void store_hi4(__half* dst, float4 v) {
    *(uint2*)dst = make_uint2(pack_h2(v.x, v.y), pack_h2(v.z, v.w));
}

// ---------------------------------------------------------------------------
// cp.async tile loader (A 128x128B, B 128x128B per chunk, SW128 swizzle)
// ---------------------------------------------------------------------------
__device__ __forceinline__ void load_tiles(uint32_t stage_base,
    const __half* __restrict__ A, const __half* __restrict__ B, int c)
{
    const int tid = threadIdx.x;
    #pragma unroll
    for (int i = 0; i < 8; ++i) {
        int idx = tid + i * THREADS;
        int row = idx >> 3, j = idx & 7;
        uint32_t d = (uint32_t)(row * 128 + ((j * 16) ^ ((row & 7) << 4)));
        CP_ASYNC16(stage_base + d,         A + (size_t)row * LD + c * KTILE + j * 8);
        CP_ASYNC16(stage_base + OFF_B + d, B + (size_t)row * LD + c * KTILE + j * 8);
    }
}

// ---------------------------------------------------------------------------
// Mainloop: acc[4][8][4] += A[128xK] * B[128xK]^T  (fp16 in, fp32 accum)
// ---------------------------------------------------------------------------
__device__ __forceinline__ void hmma_mainloop(uint32_t smem_base,
    const __half* __restrict__ Arows,
    const __half* __restrict__ Brows,
    float acc[4][8][4])
{
    const int tid  = threadIdx.x;
    const int lane = tid & 31, wid = tid >> 5;
    const int wm = wid >> 1, wn = wid & 1;

    const uint32_t aOff = (uint32_t)((wm * 64 + (lane & 15)) * 128);
    const uint32_t aKb  = (uint32_t)((lane >> 4) * 16);
    const uint32_t bOff = (uint32_t)((wn * 64 + ((lane >> 4) << 3) + (lane & 7)) * 128);
    const uint32_t bKb  = (uint32_t)(((lane >> 3) & 1) * 16);
    const uint32_t swz  = (uint32_t)((lane & 7) << 4);

    load_tiles(smem_base,               Arows, Brows, 0); CP_COMMIT();
    load_tiles(smem_base + STAGE_BYTES, Arows, Brows, 1); CP_COMMIT();

    for (int c = 0; c < NCHUNK; ++c) {
        if (c + 1 < NCHUNK) { CP_WAIT1(); } else { CP_WAIT0(); }
        __syncthreads();
        if (c + 2 < NCHUNK) {
            load_tiles(smem_base + ((c + 2) % NSTAGE) * STAGE_BYTES, Arows, Brows, c + 2);
            CP_COMMIT();
        }

        const uint32_t bufA = smem_base + (c % NSTAGE) * STAGE_BYTES;
        const uint32_t bufB = bufA + OFF_B;

        #pragma unroll
        for (int ks = 0; ks < 4; ++ks) {
            const uint32_t ak = (uint32_t)(ks * 32 + aKb) ^ swz;
            const uint32_t bk = (uint32_t)(ks * 32 + bKb) ^ swz;
            uint32_t a[4][4], b[4][4];
            #pragma unroll
            for (int fm = 0; fm < 4; ++fm) {
                uint32_t ad = bufA + aOff + fm * 2048 + ak;
                LDSM4(a[fm][0], a[fm][1], a[fm][2], a[fm][3], ad);
            }
            #pragma unroll
            for (int g = 0; g < 4; ++g) {
                uint32_t bd = bufB + bOff + g * 2048 + bk;
                LDSM4(b[g][0], b[g][1], b[g][2], b[g][3], bd);
            }
            #pragma unroll
            for (int fm = 0; fm < 4; ++fm) {
                #pragma unroll
                for (int fn = 0; fn < 8; ++fn) {
                    const int g = fn >> 1, p = (fn & 1) * 2;
                    MMA16816(acc[fm][fn], a[fm], b[g][p], b[g][p + 1]);
                }
            }
        }
    }
    __syncthreads();
}

// ---------------------------------------------------------------------------
// Launch 2 (primary for PDL): prep (bids 0..2047) + transU (2048..3071).
// Every block triggers PDL completion at start; releases per-tile counters.
// ---------------------------------------------------------------------------
__global__ __launch_bounds__(256)
void prep_all(const float* __restrict__ D, const float* __restrict__ Hf,
              const float* __restrict__ U, const float* __restrict__ W,
              __half* __restrict__ Ds, __half* __restrict__ Hs,
              __half* __restrict__ Ut,
              float* __restrict__ rowlin, float* __restrict__ collin)
{
    cudaTriggerProgrammaticLaunchCompletion();
    const int bid = blockIdx.x;
    if (bid < PREP_BLOCKS) {
        const int warp = threadIdx.x >> 5, lane = threadIdx.x & 31;
        const size_t m = (size_t)bid * 8 + warp;
        const float* drow = D + m * DD;
        const float* hrow = Hf + m * DD;
        __half* dd = Ds + m * LD;
        __half* dh = Hs + m * LD;

        float s1 = 0.f, s2 = 0.f;
        #pragma unroll
        for (int i = 0; i < 8; ++i) {
            const int c = i * 128 + lane * 4;
            float4 dv = *(const float4*)(drow + c);
            float4 hv = *(const float4*)(hrow + c);
            float4 wv = *(const float4*)(W + c);          // W[0:1024] aligned
            float w20 = __ldg(W + DD + 1 + c);
            float w21 = __ldg(W + DD + 2 + c);
            float w22 = __ldg(W + DD + 3 + c);
            float w23 = __ldg(W + DD + 4 + c);

            s1 = fmaf(dv.x, wv.x, fmaf(dv.y, wv.y, fmaf(dv.z, wv.z, fmaf(dv.w, wv.w, s1))));
            s2 = fmaf(hv.x, w20, fmaf(hv.y, w21, fmaf(hv.z, w22, fmaf(hv.w, w23, s2))));

            store_hi4(dd + c, dv);
            store_hi4(dh + c, hv);
        }
        #pragma unroll
        for (int o = 16; o > 0; o >>= 1) {
            s1 += __shfl_down_sync(0xffffffffu, s1, o);
            s2 += __shfl_down_sync(0xffffffffu, s2, o);
        }
        if (lane == 0) {
            rowlin[m] = s1 + W[DD];
            collin[m] = s2;
        }
        __syncthreads();
        if (threadIdx.x == 0) red_release(&g_prep_done[bid >> 4], 1);
    } else {
        // transpose U tile
        __shared__ float t[32][33];
        const int bid2 = bid - PREP_BLOCKS;
        const int n0 = (bid2 & 31) * 32, k0 = (bid2 >> 5) * 32;
        const int tx = threadIdx.x & 31, ty = threadIdx.x >> 5;   // (32, 8)
        #pragma unroll
        for (int i = ty; i < 32; i += 8)
            t[i][tx] = U[(size_t)(k0 + i) * DD + n0 + tx];
        __syncthreads();
        #pragma unroll
        for (int i = ty; i < 32; i += 8)
            Ut[(size_t)(n0 + i) * LD + (k0 + tx)] = __float2half_rn(t[tx][i]);
        __syncthreads();
        if (threadIdx.x == 0) red_release(&g_transU_done[(bid2 & 31) >> 2], 1);
    }
}

// ---------------------------------------------------------------------------
// Launch 3 (PDL secondary): gemm1 (bids 0..1023) + gemm2 (1024..1535).
// gemm1 spins on prep/transU counters; gemm2 on gemm1 + prep counters.
// ---------------------------------------------------------------------------
__global__ __launch_bounds__(THREADS, 2)
void gemm_fused(const __half* __restrict__ Ds, const __half* __restrict__ Hs,
                __half* __restrict__ Ts, const __half* __restrict__ Uts,
                const float* __restrict__ Ubias,
                const float* __restrict__ rowlin, const float* __restrict__ collin,
                float* __restrict__ out)
{
    extern __shared__ char smem[];
    uint32_t smem_base = smem_u32_of(smem);
    const int bid = blockIdx.x;
    const int tid = threadIdx.x;
    const int lane = tid & 31, wid = tid >> 5;
    const int wm = wid >> 1, wn = wid & 1;

    if (bid < N_G1) {
        // ---- gemm1 tile: T = Daug @ U (+bias), store fp16 ----
        const int mt = bid >> 3, nb = bid & 7;
        if (tid == 0) {
            while (ld_acquire(&g_prep_done[mt])   < 16)  __nanosleep(64);
            while (ld_acquire(&g_transU_done[nb]) < 128) __nanosleep(64);
        }
        __syncthreads();

        const size_t mBase = (size_t)mt * TM;
        const size_t nBase = (size_t)nb * TN;

        float acc[4][8][4] = {};
        hmma_mainloop(smem_base, Ds + mBase * LD, Uts + nBase * LD, acc);

        #pragma unroll
        for (int fm = 0; fm < 4; ++fm) {
            const size_t r0 = mBase + wm * 64 + fm * 16 + (lane >> 2);
            #pragma unroll
            for (int fn = 0; fn < 8; ++fn) {
                const size_t n = nBase + wn * 64 + fn * 8 + 2 * (lane & 3);
                const float b0 = Ubias[n], b1 = Ubias[n + 1];
                #pragma unroll
                for (int h = 0; h < 2; ++h) {
                    const size_t r = r0 + h * 8;
                    *(uint32_t*)(Ts + r * LD + n) =
                        pack_h2(acc[fm][fn][2 * h] + b0, acc[fm][fn][2 * h + 1] + b1);
                }
            }
        }
        __syncthreads();
        if (tid == 0) red_release(&g_gemm1_done[mt], 1);
    } else {
        // ---- gemm2 tile: out = T @ H^T + rowlin + collin ----
        const int g   = bid - N_G1;
        const int y   = g & 3;
        const int mtx = g >> 2;              // ascending with bid
        const int b   = mtx >> 2, x = mtx & 3;
        const int mty = b * 4 + y;

        if (tid == 0) {
            while (ld_acquire(&g_gemm1_done[mtx]) < 8)  __nanosleep(64);
            while (ld_acquire(&g_prep_done[mty])  < 16) __nanosleep(64);
        }
        __syncthreads();

        const size_t xBase = (size_t)x * TM;
        const size_t yBase = (size_t)y * TN;

        float acc[4][8][4] = {};
        hmma_mainloop(smem_base,
                      Ts + ((size_t)b * SEQ + xBase) * LD,
                      Hs + ((size_t)b * SEQ + yBase) * LD, acc);

        #pragma unroll
        for (int fm = 0; fm < 4; ++fm) {
            const size_t x0 = xBase + wm * 64 + fm * 16 + (lane >> 2);
            #pragma unroll
            for (int h = 0; h < 2; ++h) {
                const size_t gx = (size_t)b * SEQ + x0 + h * 8;
                const float rl = rowlin[gx];
                #pragma unroll
                for (int fn = 0; fn < 8; ++fn) {
                    const size_t yy = yBase + wn * 64 + fn * 8 + 2 * (lane & 3);
                    const float c0 = collin[(size_t)b * SEQ + yy];
                    const float c1 = collin[(size_t)b * SEQ + yy + 1];
                    float2 o;
                    o.x = acc[fm][fn][2 * h]     + rl + c0;
                    o.y = acc[fm][fn][2 * h + 1] + rl + c1;
                    *(float2*)(out + gx * SEQ + yy) = o;
                }
            }
        }
    }
}

// Launch 1: zero all dependency counters (must precede prep_all each replay)
__global__ void zero_kernel()
{
    const int t = threadIdx.x;
    if (t < N_MT)  { g_prep_done[t] = 0; g_gemm1_done[t] = 0; }
    if (t < N_NB)    g_transU_done[t] = 0;
}

// ---------------------------------------------------------------------------
extern "C" void kernel_launch(void* const* d_in, const int* in_sizes, int n_in,
                              void* d_out, int out_size)
{
    const float* D = (const float*)d_in[0];   // [32,512,1024]
    const float* H = (const float*)d_in[1];   // [32,512,1024]
    const float* U = (const float*)d_in[2];   // [1025,1024]
    const float* W = (const float*)d_in[3];   // [2049]
    float* out = (float*)d_out;               // [32,512,512]

    __half *Ds, *Hs, *Ts, *Uts;
    float *rowlin, *collin;
    cudaGetSymbolAddress((void**)&Ds,  g_Ds);
    cudaGetSymbolAddress((void**)&Hs,  g_Hs);
    cudaGetSymbolAddress((void**)&Ts,  g_Ts);
    cudaGetSymbolAddress((void**)&Uts, g_Uts);
    cudaGetSymbolAddress((void**)&rowlin, g_rowlin);
    cudaGetSymbolAddress((void**)&collin, g_collin);

    cudaFuncSetAttribute(gemm_fused, cudaFuncAttributeMaxDynamicSharedMemorySize, SMEM_TOTAL);

    // 1) zero counters
    zero_kernel<<<1, N_MT>>>();

    // 2) prep + transU (PDL primary; each block triggers at start)
    prep_all<<<PREP_BLOCKS + TRANSU_BLOCKS, 256>>>(
        D, H, U, W, Ds, Hs, Uts, rowlin, collin);

    // 3) gemm1 + gemm2, launched as PDL secondary: may begin dispatch once all
    //    prep blocks have started; per-tile spins enforce data readiness.
    cudaLaunchConfig_t cfg = {};
    cfg.gridDim  = dim3(N_G1 + N_G2, 1, 1);
    cfg.blockDim = dim3(THREADS, 1, 1);
    cfg.dynamicSmemBytes = SMEM_TOTAL;
    cudaLaunchAttribute attrs[1];
    attrs[0].id = cudaLaunchAttributeProgrammaticStreamSerialization;
    attrs[0].val.programmaticStreamSerializationAllowed = 1;
    cfg.attrs = attrs;
    cfg.numAttrs = 1;
    cudaLaunchKernelEx(&cfg, gemm_fused,
                       (const __half*)Ds, (const __half*)Hs, Ts, (const __half*)Uts,
                       (const float*)(U + (size_t)DD * DD),
                       (const float*)rowlin, (const float*)collin, out);
}